// round 3
// baseline (speedup 1.0000x reference)
#include <cuda_runtime.h>

#define NN 100000
#define EE 100000
#define D  128
#define LDP 1920

// ---------------- device scratch (no mallocs allowed) ----------------
__device__ float g_feat[NN * D];          // 51.2 MB
__device__ float g_h   [NN * D];          // 51.2 MB
__device__ float g_h2  [NN * D];          // 51.2 MB
__device__ float g_q   [NN * D];          // 51.2 MB
__device__ float g_P   [NN * LDP];        // 768 MB: [ctr(128) | 14 x edge msgs(128)]

// ---------------- packed f32x2 helpers ----------------
#define FMA2(d, a, b) asm("fma.rn.f32x2 %0, %1, %2, %0;" : "+l"(d) : "l"(a), "l"(b))
#define DUP2(d, s)    asm("mov.b64 %0, {%1, %1};" : "=l"(d) : "f"(s))
#define UNPK2(lo, hi, s) asm("mov.b64 {%0, %1}, %2;" : "=f"(lo), "=f"(hi) : "l"(s))

// ---------------- GEMM: C[n, j] = sum_k A[n,k] * B[j,k], K = 128 ----------------
// Block tile 128x128, 256 threads, micro-tile 8(m) x 8(j), f32x2 packed along j.
// 2 CTAs/SM resident -> tile-load latency of one CTA hidden by the other's mainloop.
#define BK  32
#define SST 130   // smem row stride (even -> 8B-aligned float2)

__global__ __launch_bounds__(256, 2) void gemm_rr(
    const float* __restrict__ A, int lda,
    const float* __restrict__ B, int ldb,
    float* __restrict__ C, int ldc, int nrows)
{
    __shared__ float As[BK * SST];
    __shared__ float Bs[BK * SST];
    const int tid = threadIdx.x;
    const int tx  = tid & 15;   // j group: cols j = 32*j2 + 2*tx + {0,1}, j2 = 0..3
    const int ty  = tid >> 4;   // m group: rows m = ty*8 + mm, ty = 0..15
    const int m0  = blockIdx.x * 128;
    const int n0  = blockIdx.y * 128;

    unsigned long long acc[8][4];
#pragma unroll
    for (int i = 0; i < 8; i++)
#pragma unroll
        for (int j = 0; j < 4; j++) acc[i][j] = 0ULL;

    for (int k0 = 0; k0 < 128; k0 += BK) {
        // stage tiles: 128 rows x 32 k -> transposed layout [k][row]
#pragma unroll
        for (int p = 0; p < 4; p++) {
            int flat = p * 256 + tid;
            int row  = flat >> 3;      // 0..127
            int q    = flat & 7;       // 0..7
            int kk   = q * 4;
            float4 v = make_float4(0.f, 0.f, 0.f, 0.f);
            int gr = m0 + row;
            if (gr < nrows) v = *(const float4*)(A + (long long)gr * lda + k0 + kk);
            As[(kk + 0) * SST + row] = v.x;
            As[(kk + 1) * SST + row] = v.y;
            As[(kk + 2) * SST + row] = v.z;
            As[(kk + 3) * SST + row] = v.w;
            float4 w = *(const float4*)(B + (long long)(n0 + row) * ldb + k0 + kk);
            Bs[(kk + 0) * SST + row] = w.x;
            Bs[(kk + 1) * SST + row] = w.y;
            Bs[(kk + 2) * SST + row] = w.z;
            Bs[(kk + 3) * SST + row] = w.w;
        }
        __syncthreads();
#pragma unroll 4
        for (int kk = 0; kk < BK; kk++) {
            const float* ab = As + kk * SST + ty * 8;
            const float* bb = Bs + kk * SST + tx * 2;
            unsigned long long bv[4];
#pragma unroll
            for (int j2 = 0; j2 < 4; j2++)
                bv[j2] = *(const unsigned long long*)(bb + j2 * 32);
#pragma unroll
            for (int m2 = 0; m2 < 4; m2++) {
                float2 av = *(const float2*)(ab + m2 * 2);
                unsigned long long a0, a1;
                DUP2(a0, av.x);
                DUP2(a1, av.y);
#pragma unroll
                for (int j2 = 0; j2 < 4; j2++) {
                    FMA2(acc[m2 * 2 + 0][j2], a0, bv[j2]);
                    FMA2(acc[m2 * 2 + 1][j2], a1, bv[j2]);
                }
            }
        }
        __syncthreads();
    }
#pragma unroll
    for (int mm = 0; mm < 8; mm++) {
        int gm = m0 + ty * 8 + mm;
        if (gm >= nrows) continue;
        float* crow = C + (long long)gm * ldc + n0 + tx * 2;
#pragma unroll
        for (int j2 = 0; j2 < 4; j2++) {
            float lo, hi;
            UNPK2(lo, hi, acc[mm][j2]);
            float2 o = make_float2(lo, hi);
            *(float2*)(crow + j2 * 32) = o;
        }
    }
}

// ---------------- scatter: P[dst, 0:128] += P[src, 128 + 128*t : ...] ----------------
__global__ __launch_bounds__(256) void scatter_k(
    const int* __restrict__ idx, const int* __restrict__ mask,
    float* __restrict__ P, int ne)
{
    int gw   = (blockIdx.x * blockDim.x + threadIdx.x) >> 5;
    int lane = threadIdx.x & 31;
    if (gw >= 14 * ne) return;
    int t = gw / ne;
    int e = gw - t * ne;
    if (e >= __ldg(&mask[t])) return;
    int dst = __ldg(&idx[e * 28 + 2 * t]);
    int src = __ldg(&idx[e * 28 + 2 * t + 1]);
    float4 v = *(const float4*)(P + (long long)src * LDP + 128 + t * 128 + lane * 4);
    float* p = P + (long long)dst * LDP + lane * 4;
    asm volatile("red.global.add.v4.f32 [%0], {%1,%2,%3,%4};"
                 :: "l"(p), "f"(v.x), "f"(v.y), "f"(v.z), "f"(v.w) : "memory");
}

// ---------------- GroupNorm(1 group) helpers: 1 warp per row of 128 ----------------
__device__ __forceinline__ void gn_stats(float s1, float s2, float& mean, float& inv)
{
#pragma unroll
    for (int o = 16; o > 0; o >>= 1) {
        s1 += __shfl_xor_sync(0xffffffffu, s1, o);
        s2 += __shfl_xor_sync(0xffffffffu, s2, o);
    }
    mean = s1 * (1.f / 128.f);
    float var = s2 * (1.f / 128.f) - mean * mean;
    inv = rsqrtf(var + 1e-5f);
}

// out = relu(GN(X[:, :128] with row stride ldx))
__global__ __launch_bounds__(256) void gn_relu_k(
    const float* __restrict__ X, int ldx,
    const float* __restrict__ g, const float* __restrict__ b,
    float* __restrict__ out, int n)
{
    int gt = blockIdx.x * blockDim.x + threadIdx.x;
    int row = gt >> 5, lane = gt & 31;
    if (row >= n) return;
    float4 v = *(const float4*)(X + (long long)row * ldx + lane * 4);
    float m, inv;
    gn_stats(v.x + v.y + v.z + v.w, v.x * v.x + v.y * v.y + v.z * v.z + v.w * v.w, m, inv);
    float4 gg = *(const float4*)(g + lane * 4);
    float4 bb = *(const float4*)(b + lane * 4);
    float4 o;
    o.x = fmaxf((v.x - m) * inv * gg.x + bb.x, 0.f);
    o.y = fmaxf((v.y - m) * inv * gg.y + bb.y, 0.f);
    o.z = fmaxf((v.z - m) * inv * gg.z + bb.z, 0.f);
    o.w = fmaxf((v.w - m) * inv * gg.w + bb.w, 0.f);
    *(float4*)(out + (long long)row * 128 + lane * 4) = o;
}

// feat = relu(GN(Q) + feat)   (feat read+written in place; res == feat at loop entry)
__global__ __launch_bounds__(256) void gn_add_relu_k(
    const float* __restrict__ Q,
    const float* __restrict__ g, const float* __restrict__ b,
    float* __restrict__ feat, int n)
{
    int gt = blockIdx.x * blockDim.x + threadIdx.x;
    int row = gt >> 5, lane = gt & 31;
    if (row >= n) return;
    float4 v = *(const float4*)(Q + (long long)row * 128 + lane * 4);
    float m, inv;
    gn_stats(v.x + v.y + v.z + v.w, v.x * v.x + v.y * v.y + v.z * v.z + v.w * v.w, m, inv);
    float4 gg = *(const float4*)(g + lane * 4);
    float4 bb = *(const float4*)(b + lane * 4);
    float4 f  = *(const float4*)(feat + (long long)row * 128 + lane * 4);
    float4 o;
    o.x = fmaxf((v.x - m) * inv * gg.x + bb.x + f.x, 0.f);
    o.y = fmaxf((v.y - m) * inv * gg.y + bb.y + f.y, 0.f);
    o.z = fmaxf((v.z - m) * inv * gg.z + bb.z + f.z, 0.f);
    o.w = fmaxf((v.w - m) * inv * gg.w + bb.w + f.w, 0.f);
    *(float4*)(feat + (long long)row * 128 + lane * 4) = o;
}

// out = relu(GN(U, gU,bU) + GN(V, gV,bV))
__global__ __launch_bounds__(256) void gn_combine_k(
    const float* __restrict__ U,
    const float* __restrict__ gU, const float* __restrict__ bU,
    const float* __restrict__ V,
    const float* __restrict__ gV, const float* __restrict__ bV,
    float* __restrict__ out, int n)
{
    int gt = blockIdx.x * blockDim.x + threadIdx.x;
    int row = gt >> 5, lane = gt & 31;
    if (row >= n) return;
    float4 u = *(const float4*)(U + (long long)row * 128 + lane * 4);
    float4 v = *(const float4*)(V + (long long)row * 128 + lane * 4);
    float mu, iu, mv, iv;
    gn_stats(u.x + u.y + u.z + u.w, u.x * u.x + u.y * u.y + u.z * u.z + u.w * u.w, mu, iu);
    gn_stats(v.x + v.y + v.z + v.w, v.x * v.x + v.y * v.y + v.z * v.z + v.w * v.w, mv, iv);
    float4 g1 = *(const float4*)(gU + lane * 4), b1 = *(const float4*)(bU + lane * 4);
    float4 g2 = *(const float4*)(gV + lane * 4), b2 = *(const float4*)(bV + lane * 4);
    float4 o;
    o.x = fmaxf((u.x - mu) * iu * g1.x + b1.x + (v.x - mv) * iv * g2.x + b2.x, 0.f);
    o.y = fmaxf((u.y - mu) * iu * g1.y + b1.y + (v.y - mv) * iv * g2.y + b2.y, 0.f);
    o.z = fmaxf((u.z - mu) * iu * g1.z + b1.z + (v.z - mv) * iv * g2.z + b2.z, 0.f);
    o.w = fmaxf((u.w - mu) * iu * g1.w + b1.w + (v.w - mv) * iv * g2.w + b2.w, 0.f);
    *(float4*)(out + (long long)row * 128 + lane * 4) = o;
}

// feat = relu(GN(M + nodes[:,4:8] @ meta_W[:,128:132].T))
__global__ __launch_bounds__(256) void gn_meta_k(
    const float* __restrict__ M, const float* __restrict__ nodes,
    const float* __restrict__ metaW,
    const float* __restrict__ g, const float* __restrict__ b,
    float* __restrict__ out, int n)
{
    int gt = blockIdx.x * blockDim.x + threadIdx.x;
    int row = gt >> 5, lane = gt & 31;
    if (row >= n) return;
    float4 x = *(const float4*)(M + (long long)row * 128 + lane * 4);
    float4 e = *(const float4*)(nodes + (long long)row * 8 + 4);
    int c0 = lane * 4;
    float4 w0 = *(const float4*)(metaW + (long long)(c0 + 0) * 132 + 128);
    float4 w1 = *(const float4*)(metaW + (long long)(c0 + 1) * 132 + 128);
    float4 w2 = *(const float4*)(metaW + (long long)(c0 + 2) * 132 + 128);
    float4 w3 = *(const float4*)(metaW + (long long)(c0 + 3) * 132 + 128);
    x.x += w0.x * e.x + w0.y * e.y + w0.z * e.z + w0.w * e.w;
    x.y += w1.x * e.x + w1.y * e.y + w1.z * e.z + w1.w * e.w;
    x.z += w2.x * e.x + w2.y * e.y + w2.z * e.z + w2.w * e.w;
    x.w += w3.x * e.x + w3.y * e.y + w3.z * e.z + w3.w * e.w;
    float m, inv;
    gn_stats(x.x + x.y + x.z + x.w, x.x * x.x + x.y * x.y + x.z * x.z + x.w * x.w, m, inv);
    float4 gg = *(const float4*)(g + lane * 4);
    float4 bb = *(const float4*)(b + lane * 4);
    float4 o;
    o.x = fmaxf((x.x - m) * inv * gg.x + bb.x, 0.f);
    o.y = fmaxf((x.y - m) * inv * gg.y + bb.y, 0.f);
    o.z = fmaxf((x.z - m) * inv * gg.z + bb.z, 0.f);
    o.w = fmaxf((x.w - m) * inv * gg.w + bb.w, 0.f);
    *(float4*)(out + (long long)row * 128 + lane * 4) = o;
}

// h1 = relu(nodes[:,0:2]@in1_W.T + in1_b); h2 = relu(nodes[:,2:4]@seg1_W.T + seg1_b)
__global__ __launch_bounds__(256) void lin_in_k(
    const float* __restrict__ nodes,
    const float* __restrict__ w1, const float* __restrict__ b1,
    const float* __restrict__ w2, const float* __restrict__ b2,
    float* __restrict__ h1, float* __restrict__ h2, int n)
{
    int i = blockIdx.x * blockDim.x + threadIdx.x;
    if (i >= n * 128) return;
    int node = i >> 7, c = i & 127;
    const float* xr = nodes + (long long)node * 8;
    float x0 = __ldg(xr + 0), x1 = __ldg(xr + 1), x2 = __ldg(xr + 2), x3 = __ldg(xr + 3);
    float a = fmaf(__ldg(w1 + c * 2), x0, fmaf(__ldg(w1 + c * 2 + 1), x1, __ldg(b1 + c)));
    float s = fmaf(__ldg(w2 + c * 2), x2, fmaf(__ldg(w2 + c * 2 + 1), x3, __ldg(b2 + c)));
    h1[i] = fmaxf(a, 0.f);
    h2[i] = fmaxf(s, 0.f);
}

// output = (feat flattened, nodes[:, :2] flattened)
__global__ __launch_bounds__(256) void out_copy_k(
    const float* __restrict__ feat, const float* __restrict__ nodes,
    float* __restrict__ out, int n, int tot)
{
    int i = blockIdx.x * blockDim.x + threadIdx.x;
    if (i >= tot) return;
    int nf = n * 128;
    if (i < nf) out[i] = feat[i];
    else { int j = i - nf; out[i] = nodes[(long long)(j >> 1) * 8 + (j & 1)]; }
}

// ---------------- launcher ----------------
extern "C" void kernel_launch(void* const* d_in, const int* in_sizes, int n_in,
                              void* d_out, int out_size)
{
    const float* nodes   = (const float*)d_in[0];
    const int*   idx     = (const int*)  d_in[1];
    const int*   mask    = (const int*)  d_in[2];
    const float* in1_W   = (const float*)d_in[3];
    const float* in1_b   = (const float*)d_in[4];
    const float* in2_W   = (const float*)d_in[5];
    const float* in_g    = (const float*)d_in[6];
    const float* in_bg   = (const float*)d_in[7];
    const float* seg1_W  = (const float*)d_in[8];
    const float* seg1_b  = (const float*)d_in[9];
    const float* seg2_W  = (const float*)d_in[10];
    const float* seg_g   = (const float*)d_in[11];
    const float* seg_bg  = (const float*)d_in[12];
    const float* meta_W  = (const float*)d_in[13];
    const float* meta_g  = (const float*)d_in[14];
    const float* meta_bg = (const float*)d_in[15];
    const float* ctr_W   = (const float*)d_in[16];
    const float* edge_W  = (const float*)d_in[17];
    const float* norm_g  = (const float*)d_in[18];
    const float* norm_bg = (const float*)d_in[19];
    const float* ctr2_W  = (const float*)d_in[20];
    const float* ctr2_g  = (const float*)d_in[21];
    const float* ctr2_bg = (const float*)d_in[22];
    float* out = (float*)d_out;

    const int n = in_sizes[0] / 8;    // 100000
    const int e = in_sizes[1] / 28;   // 100000

    float *feat, *h, *h2, *q, *P;
    cudaGetSymbolAddress((void**)&feat, g_feat);
    cudaGetSymbolAddress((void**)&h,    g_h);
    cudaGetSymbolAddress((void**)&h2,   g_h2);
    cudaGetSymbolAddress((void**)&q,    g_q);
    cudaGetSymbolAddress((void**)&P,    g_P);

    const int mt        = (n + 127) / 128;
    const int gn_blocks = (n * 32 + 255) / 256;

    // ---- input / seg / meta stage ----
    lin_in_k<<<(n * 128 + 255) / 256, 256>>>(nodes, in1_W, in1_b, seg1_W, seg1_b, h, h2, n);
    gemm_rr<<<dim3(mt, 1), 256>>>(h,  128, in2_W,  128, q, 128, n);
    gemm_rr<<<dim3(mt, 1), 256>>>(h2, 128, seg2_W, 128, P, 128, n);   // P as N x 128 scratch
    gn_combine_k<<<gn_blocks, 256>>>(q, in_g, in_bg, P, seg_g, seg_bg, h, n);
    gemm_rr<<<dim3(mt, 1), 256>>>(h, 128, meta_W, 132, q, 128, n);    // K = first 128 cols
    gn_meta_k<<<gn_blocks, 256>>>(q, nodes, meta_W, meta_g, meta_bg, feat, n);

    // ---- 4 message-passing layers ----
    const int sc_blocks = (14 * e * 32 + 255) / 256;
    for (int i = 0; i < 4; i++) {
        // P[:, 0:128]   = feat @ ctr_W[i].T
        gemm_rr<<<dim3(mt, 1), 256>>>(feat, 128, ctr_W + (long long)i * 16384, 128, P, LDP, n);
        // P[:, 128:1920] = feat @ [edge_W[i,0..13]].T  (14 stacked 128x128 matrices)
        gemm_rr<<<dim3(mt, 14), 256>>>(feat, 128, edge_W + (long long)i * 14 * 16384, 128,
                                       P + 128, LDP, n);
        // P[dst, 0:128] += P[src, msg_t]  (L2-resident vector atomics)
        scatter_k<<<sc_blocks, 256>>>(idx, mask, P, e);
        // h = relu(GN(P[:, :128]))
        gn_relu_k<<<gn_blocks, 256>>>(P, LDP, norm_g + i * 128, norm_bg + i * 128, h, n);
        // q = h @ ctr2_W[i].T
        gemm_rr<<<dim3(mt, 1), 256>>>(h, 128, ctr2_W + (long long)i * 16384, 128, q, 128, n);
        // feat = relu(GN(q) + feat)
        gn_add_relu_k<<<gn_blocks, 256>>>(q, ctr2_g + i * 128, ctr2_bg + i * 128, feat, n);
    }

    int tot = n * 130;
    if (tot > out_size) tot = out_size;
    out_copy_k<<<(tot + 255) / 256, 256>>>(feat, nodes, out, n, tot);
}